// round 5
// baseline (speedup 1.0000x reference)
#include <cuda_runtime.h>
#include <cstdint>

#define NQ_CAP   20000
#define E_CAP    640000
#define DF       128

// ---------------- static device scratch -------------------------------------
__device__ int      g_counts [NQ_CAP];
__device__ int      g_offsets[NQ_CAP + 1];
__device__ int      g_cursor [NQ_CAP];
__device__ int      g_eids   [E_CAP];
__device__ int      g_erow   [E_CAP];
__device__ float    g_agg    [(size_t)NQ_CAP * DF];
__device__ uint32_t g_w1n[256 * 128];
__device__ uint32_t g_w2n[128 * 128];

// ---------------- helpers ---------------------------------------------------
__device__ __forceinline__ uint32_t f2tf(float x) {
    uint32_t u; asm("cvt.rna.tf32.f32 %0, %1;" : "=r"(u) : "f"(x)); return u;
}
__device__ __forceinline__ float silu(float x) { return x / (1.0f + __expf(-x)); }
__device__ __forceinline__ void mma8(float c[4], const uint32_t a[4],
                                     uint32_t b0, uint32_t b1) {
    asm("mma.sync.aligned.m16n8k8.row.col.f32.tf32.tf32.f32 "
        "{%0,%1,%2,%3}, {%4,%5,%6,%7}, {%8,%9}, {%0,%1,%2,%3};"
        : "+f"(c[0]), "+f"(c[1]), "+f"(c[2]), "+f"(c[3])
        : "r"(a[0]), "r"(a[1]), "r"(a[2]), "r"(a[3]), "r"(b0), "r"(b1));
}

// ---------------- CSR build -------------------------------------------------
__global__ void zero_kernel(int nq) {
    int i = blockIdx.x * blockDim.x + threadIdx.x;
    if (i < nq) g_counts[i] = 0;
    if (i < nq * DF) g_agg[i] = 0.f;
}
__global__ void hist_kernel(const int* __restrict__ ei, int E) {
    int e = blockIdx.x * blockDim.x + threadIdx.x;
    if (e < E) atomicAdd(&g_counts[ei[e]], 1);
}
__global__ void scan_kernel(int nq) {
    const int CH = 20;
    __shared__ int wt[32];
    int tid = threadIdx.x, lane = tid & 31, w = tid >> 5;
    int loc[CH]; int base = tid * CH; int s = 0;
#pragma unroll
    for (int i = 0; i < CH; i++) {
        loc[i] = (base + i < nq) ? g_counts[base + i] : 0; s += loc[i];
    }
    int v = s;
#pragma unroll
    for (int o = 1; o < 32; o <<= 1) { int t = __shfl_up_sync(~0u, v, o); if (lane >= o) v += t; }
    if (lane == 31) wt[w] = v;
    __syncthreads();
    if (w == 0) {
        int x = wt[lane];
#pragma unroll
        for (int o = 1; o < 32; o <<= 1) { int t = __shfl_up_sync(~0u, x, o); if (lane >= o) x += t; }
        wt[lane] = x;
    }
    __syncthreads();
    int ex = v + (w ? wt[w - 1] : 0) - s;
#pragma unroll
    for (int i = 0; i < CH; i++) {
        if (base + i < nq) { g_offsets[base + i] = ex; g_cursor[base + i] = ex; }
        ex += loc[i];
    }
    if (tid == 1023) g_offsets[nq] = ex;
}
__global__ void scatter_kernel(const int* __restrict__ ei, int E) {
    int e = blockIdx.x * blockDim.x + threadIdx.x;
    if (e < E) {
        int r = ei[e];
        int pos = atomicAdd(&g_cursor[r], 1);
        g_eids[pos] = e; g_erow[pos] = r;
    }
}

// ---------------- edge MLP: persistent, weights-in-smem ---------------------
// SMEM (uint32 units):
//   W1s [0, 32768)     256x128 tf32, layout (k/4)*512 + n*4 + k%4
//   W2s [32768, 49152) 128x128 tf32, same layout
//   A   [49152, 53248) 16 x 256 tf32, XOR swizzle (col ^ 4*(row&7)); aliased as Rb fp32
//   Hs  [53248, 55296) 16 x 128 tf32, same swizzle
//   s_eid [55296,55312) s_row [55312,55328)
#define EW1  0
#define EW2  32768
#define EA   49152
#define EH   53248
#define EEID 55296
#define EROW 55312
#define SMEM_E (55328 * 4)

__global__ void __launch_bounds__(256, 1)
edge_mlp_kernel(const float* __restrict__ h_q, const float* __restrict__ h_kv,
                const int* __restrict__ ei, int E,
                const float* __restrict__ W1, const float* __restrict__ W2,
                const float* __restrict__ b1, const float* __restrict__ b2,
                float* __restrict__ out_m) {
    extern __shared__ uint32_t S[];
    uint32_t* W1s = S + EW1;
    uint32_t* W2s = S + EW2;
    uint32_t* A   = S + EA;
    float*    Rb  = (float*)(S + EA);
    uint32_t* Hs  = S + EH;
    int* s_eid = (int*)(S + EEID);
    int* s_row = (int*)(S + EROW);

    int tid = threadIdx.x, lane = tid & 31, wid = tid >> 5;
    int gid = lane >> 2, tg = lane & 3;
    int wbase = wid * 16;

    // ---- stage weights once (interleaved k-chunk layout) ----
    for (int i = tid; i < 32768; i += 256) {
        int k = i >> 7, n = i & 127;
        W1s[(k >> 2) * 512 + n * 4 + (k & 3)] = f2tf(W1[i]);
    }
    for (int i = tid; i < 16384; i += 256) {
        int k = i >> 7, n = i & 127;
        W2s[(k >> 2) * 512 + n * 4 + (k & 3)] = f2tf(W2[i]);
    }
    // biases (per-thread registers)
    float b1v[2][2], b2v[2][2];
#pragma unroll
    for (int nt = 0; nt < 2; nt++) {
        int col = wbase + nt * 8 + tg * 2;
        b1v[nt][0] = b1[col]; b1v[nt][1] = b1[col + 1];
        b2v[nt][0] = b2[col]; b2v[nt][1] = b2[col + 1];
    }
    __syncthreads();

    uint32_t swz = ((uint32_t)(gid & 7)) << 2;
    int ntiles = (E + 15) >> 4;

    for (int tile = blockIdx.x; tile < ntiles; tile += gridDim.x) {
        // ---- gather 16 edges x 256 features (CSR order) ----
        {
            int row = tid >> 4, tpr = tid & 15;
            int ci = tile * 16 + row;
            int eid = -1, qr = 0, cv = 0;
            if (ci < E) { eid = g_eids[ci]; qr = g_erow[ci]; cv = ei[E + eid]; }
            if (tpr == 0) { s_eid[row] = eid; s_row[row] = (eid >= 0) ? qr : -1; }
            int cb = tpr * 16;
            const float4* src = (cb < 128)
                ? (const float4*)(h_q + (size_t)qr * DF + cb)
                : (const float4*)(h_kv + (size_t)cv * DF + (cb - 128));
            uint32_t sw = ((uint32_t)(row & 7)) << 2;
#pragma unroll
            for (int j = 0; j < 4; j++) {
                float4 v = (eid >= 0) ? src[j] : make_float4(0.f, 0.f, 0.f, 0.f);
                uint4 u; u.x = f2tf(v.x); u.y = f2tf(v.y); u.z = f2tf(v.z); u.w = f2tf(v.w);
                *(uint4*)&A[row * 256 + ((cb + j * 4) ^ sw)] = u;
            }
        }
        __syncthreads();

        // ---- layer 1: out1[16][128] = A @ W1 (+b1) ----
        float acc[2][4];
#pragma unroll
        for (int nt = 0; nt < 2; nt++) {
            acc[nt][0] = b1v[nt][0]; acc[nt][1] = b1v[nt][1];
            acc[nt][2] = b1v[nt][0]; acc[nt][3] = b1v[nt][1];
        }
#pragma unroll
        for (int ks = 0; ks < 32; ks++) {
            int k0 = ks * 8;
            uint32_t a[4];
            a[0] = A[gid * 256       + ((k0 + tg)     ^ swz)];
            a[1] = A[(gid + 8) * 256 + ((k0 + tg)     ^ swz)];
            a[2] = A[gid * 256       + ((k0 + tg + 4) ^ swz)];
            a[3] = A[(gid + 8) * 256 + ((k0 + tg + 4) ^ swz)];
            const uint32_t* bp = W1s + (k0 >> 2) * 512;
#pragma unroll
            for (int nt = 0; nt < 2; nt++) {
                int n = wbase + nt * 8 + gid;
                mma8(acc[nt], a, bp[n * 4 + tg], bp[512 + n * 4 + tg]);
            }
        }

        // ---- silu -> H (tf32, swizzled) ----
#pragma unroll
        for (int nt = 0; nt < 2; nt++) {
            int col = wbase + nt * 8 + tg * 2;
            uint32_t s0 = ((uint32_t)(gid & 7)) << 2;
            Hs[gid * 128       + ( col      ^ s0)] = f2tf(silu(acc[nt][0]));
            Hs[gid * 128       + ((col + 1) ^ s0)] = f2tf(silu(acc[nt][1]));
            Hs[(gid + 8) * 128 + ( col      ^ s0)] = f2tf(silu(acc[nt][2]));
            Hs[(gid + 8) * 128 + ((col + 1) ^ s0)] = f2tf(silu(acc[nt][3]));
        }
        __syncthreads();

        // ---- layer 2: out2[16][128] = H @ W2 (+b2) ----
        float acc2[2][4];
#pragma unroll
        for (int nt = 0; nt < 2; nt++) {
            acc2[nt][0] = b2v[nt][0]; acc2[nt][1] = b2v[nt][1];
            acc2[nt][2] = b2v[nt][0]; acc2[nt][3] = b2v[nt][1];
        }
#pragma unroll
        for (int ks = 0; ks < 16; ks++) {
            int k0 = ks * 8;
            uint32_t a[4];
            a[0] = Hs[gid * 128       + ((k0 + tg)     ^ swz)];
            a[1] = Hs[(gid + 8) * 128 + ((k0 + tg)     ^ swz)];
            a[2] = Hs[gid * 128       + ((k0 + tg + 4) ^ swz)];
            a[3] = Hs[(gid + 8) * 128 + ((k0 + tg + 4) ^ swz)];
            const uint32_t* bp = W2s + (k0 >> 2) * 512;
#pragma unroll
            for (int nt = 0; nt < 2; nt++) {
                int n = wbase + nt * 8 + gid;
                mma8(acc2[nt], a, bp[n * 4 + tg], bp[512 + n * 4 + tg]);
            }
        }

        // ---- silu -> Rb (fp32, plain layout; aliases A which is now dead) ----
#pragma unroll
        for (int nt = 0; nt < 2; nt++) {
            int col = wbase + nt * 8 + tg * 2;
            Rb[gid * 128 + col]            = silu(acc2[nt][0]);
            Rb[gid * 128 + col + 1]        = silu(acc2[nt][1]);
            Rb[(gid + 8) * 128 + col]      = silu(acc2[nt][2]);
            Rb[(gid + 8) * 128 + col + 1]  = silu(acc2[nt][3]);
        }
        __syncthreads();

        // ---- coalesced mij store + fused segmented aggregation ----
#pragma unroll
        for (int rep = 0; rep < 2; rep++) {
            int i = tid + rep * 256;        // 512 float4 = 16 rows x 32 f4
            int row = i >> 5, c4 = i & 31;
            int eid = s_eid[row];
            if (eid >= 0) {
                float4 v = *(float4*)&Rb[row * 128 + c4 * 4];
                *(float4*)(out_m + (size_t)eid * DF + c4 * 4) = v;
            }
        }
        {
            int col = tid & 127, half = tid >> 7;
            int cur = -1; float racc = 0.f;
#pragma unroll
            for (int r = 0; r < 8; r++) {
                int rr = half * 8 + r;
                int rw = s_row[rr];
                if (rw != cur) {
                    if (cur >= 0) atomicAdd(&g_agg[(size_t)cur * DF + col], racc);
                    cur = rw; racc = 0.f;
                }
                if (rw >= 0) racc += Rb[rr * 128 + col];
            }
            if (cur >= 0) atomicAdd(&g_agg[(size_t)cur * DF + col], racc);
        }
        __syncthreads();   // protect A/H/s_* before next tile
    }
}

// ---------------- node MLP (proven R3 path) ---------------------------------
#define LDA 260
#define SMEM_N (128 * LDA * 4)

__global__ void prep_weights(const float* __restrict__ wn1,
                             const float* __restrict__ wn2) {
    int i = blockIdx.x * blockDim.x + threadIdx.x;
    if (i < 32768)       g_w1n[i]         = f2tf(wn1[i]);
    else if (i < 49152)  g_w2n[i - 32768] = f2tf(wn2[i - 32768]);
}
__device__ __forceinline__ void mma_tiles(const uint32_t* __restrict__ As,
                                          const uint32_t* __restrict__ Bw,
                                          int ksteps, float acc[2][8][4],
                                          int warp_m, int warp_n, int gid, int tg) {
    for (int ks = 0; ks < ksteps; ks++) {
        int k0 = ks * 8;
        uint32_t a[2][4];
#pragma unroll
        for (int mt = 0; mt < 2; mt++) {
            const uint32_t* ap = As + (warp_m * 32 + mt * 16 + gid) * LDA + k0 + tg;
            a[mt][0] = ap[0]; a[mt][1] = ap[8 * LDA];
            a[mt][2] = ap[4]; a[mt][3] = ap[8 * LDA + 4];
        }
#pragma unroll
        for (int nt = 0; nt < 8; nt++) {
            int n = warp_n * 64 + nt * 8 + gid;
            uint32_t b0 = Bw[(k0 + tg) * 128 + n];
            uint32_t b1 = Bw[(k0 + tg + 4) * 128 + n];
#pragma unroll
            for (int mt = 0; mt < 2; mt++) mma8(acc[mt][nt], a[mt], b0, b1);
        }
    }
}
__global__ void __launch_bounds__(256, 1)
node_kernel(const float* __restrict__ Aq,
            const float* __restrict__ bias1, const float* __restrict__ bias2,
            float* __restrict__ outp, int nrows) {
    extern __shared__ uint32_t As[];
    int tid = threadIdx.x;
    {
        int r = tid >> 1, half = tid & 1;
        int rowg = blockIdx.x * 128 + r;
        bool ok = rowg < nrows;
        int n = ok ? rowg : 0;
        const float4* src = half ? (const float4*)(g_agg + (size_t)n * DF)
                                 : (const float4*)(Aq + (size_t)n * DF);
#pragma unroll
        for (int j = 0; j < 32; j++) {
            float4 v = ok ? src[j] : make_float4(0.f, 0.f, 0.f, 0.f);
            uint4 u; u.x = f2tf(v.x); u.y = f2tf(v.y); u.z = f2tf(v.z); u.w = f2tf(v.w);
            *(uint4*)&As[r * LDA + (half * 32 + j) * 4] = u;
        }
    }
    __syncthreads();
    int lane = tid & 31, wid = tid >> 5;
    int warp_m = wid >> 1, warp_n = wid & 1;
    int gid = lane >> 2, tg = lane & 3;

    float acc[2][8][4];
#pragma unroll
    for (int nt = 0; nt < 8; nt++) {
        int col = warp_n * 64 + nt * 8 + tg * 2;
        float b0 = bias1[col], b1 = bias1[col + 1];
#pragma unroll
        for (int mt = 0; mt < 2; mt++) {
            acc[mt][nt][0] = b0; acc[mt][nt][1] = b1;
            acc[mt][nt][2] = b0; acc[mt][nt][3] = b1;
        }
    }
    mma_tiles(As, g_w1n, 32, acc, warp_m, warp_n, gid, tg);
    __syncthreads();
#pragma unroll
    for (int mt = 0; mt < 2; mt++) {
        int row = warp_m * 32 + mt * 16 + gid;
#pragma unroll
        for (int nt = 0; nt < 8; nt++) {
            int col = warp_n * 64 + nt * 8 + tg * 2;
            As[row * LDA + col]           = f2tf(silu(acc[mt][nt][0]));
            As[row * LDA + col + 1]       = f2tf(silu(acc[mt][nt][1]));
            As[(row + 8) * LDA + col]     = f2tf(silu(acc[mt][nt][2]));
            As[(row + 8) * LDA + col + 1] = f2tf(silu(acc[mt][nt][3]));
        }
    }
    __syncthreads();
#pragma unroll
    for (int nt = 0; nt < 8; nt++) {
        int col = warp_n * 64 + nt * 8 + tg * 2;
        float b0 = bias2[col], b1 = bias2[col + 1];
#pragma unroll
        for (int mt = 0; mt < 2; mt++) {
            acc[mt][nt][0] = b0; acc[mt][nt][1] = b1;
            acc[mt][nt][2] = b0; acc[mt][nt][3] = b1;
        }
    }
    mma_tiles(As, g_w2n, 16, acc, warp_m, warp_n, gid, tg);
#pragma unroll
    for (int mt = 0; mt < 2; mt++) {
        int row = warp_m * 32 + mt * 16 + gid;
        int rg0 = blockIdx.x * 128 + row, rg1 = rg0 + 8;
#pragma unroll
        for (int nt = 0; nt < 8; nt++) {
            int col = warp_n * 64 + nt * 8 + tg * 2;
            if (rg0 < nrows) {
                const float* h = Aq + (size_t)rg0 * DF + col;
                float* o = outp + (size_t)rg0 * DF + col;
                o[0] = acc[mt][nt][0] + h[0]; o[1] = acc[mt][nt][1] + h[1];
            }
            if (rg1 < nrows) {
                const float* h = Aq + (size_t)rg1 * DF + col;
                float* o = outp + (size_t)rg1 * DF + col;
                o[0] = acc[mt][nt][2] + h[0]; o[1] = acc[mt][nt][3] + h[1];
            }
        }
    }
}

// ---------------- launch ----------------------------------------------------
extern "C" void kernel_launch(void* const* d_in, const int* in_sizes, int n_in,
                              void* d_out, int out_size) {
    const float* h_q  = (const float*)d_in[0];
    const float* h_kv = (const float*)d_in[1];
    const int*   ei   = (const int*)d_in[2];
    const float* We1  = (const float*)d_in[3];
    const float* be1  = (const float*)d_in[4];
    const float* We2  = (const float*)d_in[5];
    const float* be2  = (const float*)d_in[6];
    const float* Wn1  = (const float*)d_in[7];
    const float* bn1  = (const float*)d_in[8];
    const float* Wn2  = (const float*)d_in[9];
    const float* bn2  = (const float*)d_in[10];

    int nq = in_sizes[0] / DF;
    int E  = in_sizes[2] / 2;

    float* out_h = (float*)d_out;
    float* out_m = (float*)d_out + (size_t)nq * DF;

    static int nsm = 0;
    if (!nsm) cudaDeviceGetAttribute(&nsm, cudaDevAttrMultiProcessorCount, 0);

    cudaFuncSetAttribute(edge_mlp_kernel,
                         cudaFuncAttributeMaxDynamicSharedMemorySize, SMEM_E);
    cudaFuncSetAttribute(node_kernel,
                         cudaFuncAttributeMaxDynamicSharedMemorySize, SMEM_N);

    prep_weights<<<(49152 + 255) / 256, 256>>>(Wn1, Wn2);
    zero_kernel<<<(nq * DF + 255) / 256, 256>>>(nq);
    hist_kernel<<<(E + 255) / 256, 256>>>(ei, E);
    scan_kernel<<<1, 1024>>>(nq);
    scatter_kernel<<<(E + 255) / 256, 256>>>(ei, E);

    edge_mlp_kernel<<<nsm, 256, SMEM_E>>>(h_q, h_kv, ei, E, We1, We2, be1, be2, out_m);

    node_kernel<<<(nq + 127) / 128, 256, SMEM_N>>>(h_q, bn1, bn2, out_h, nq);
}

// round 7
// speedup vs baseline: 2.3842x; 2.3842x over previous
#include <cuda_runtime.h>
#include <cstdint>

#define NQ_CAP 20000
#define E_CAP  640000
#define DF     128
#define LDA2   132            // padded row stride (words) -> conflict-free frags

// ---------------- static device scratch -------------------------------------
__device__ int      g_counts [NQ_CAP];
__device__ int      g_offsets[NQ_CAP + 1];
__device__ int      g_cursor [NQ_CAP];
__device__ int      g_eids   [E_CAP];
__device__ int      g_erow   [E_CAP];
__device__ float    g_agg    [(size_t)NQ_CAP * DF];
__device__ float    g_P      [(size_t)NQ_CAP * DF];   // h_q @ We1_top + b1
__device__ float    g_Q      [(size_t)NQ_CAP * DF];   // h_kv @ We1_bot
__device__ uint2    g_w1tp[8192];   // packed tf32 frag pairs: [ks][tg][n]
__device__ uint2    g_w1bp[8192];
__device__ uint2    g_w2ep[8192];
__device__ uint32_t g_w1n[256 * 128];
__device__ uint32_t g_w2n[128 * 128];

// ---------------- helpers ---------------------------------------------------
__device__ __forceinline__ uint32_t f2tf(float x) {
    uint32_t u; asm("cvt.rna.tf32.f32 %0, %1;" : "=r"(u) : "f"(x)); return u;
}
__device__ __forceinline__ float silu(float x) { return x / (1.0f + __expf(-x)); }
__device__ __forceinline__ void mma8(float c[4], const uint32_t a[4],
                                     uint32_t b0, uint32_t b1) {
    asm("mma.sync.aligned.m16n8k8.row.col.f32.tf32.tf32.f32 "
        "{%0,%1,%2,%3}, {%4,%5,%6,%7}, {%8,%9}, {%0,%1,%2,%3};"
        : "+f"(c[0]), "+f"(c[1]), "+f"(c[2]), "+f"(c[3])
        : "r"(a[0]), "r"(a[1]), "r"(a[2]), "r"(a[3]), "r"(b0), "r"(b1));
}

// ---------------- prep: packed tf32 weights ---------------------------------
__global__ void prep_weights(const float* __restrict__ We1,
                             const float* __restrict__ We2,
                             const float* __restrict__ Wn1,
                             const float* __restrict__ Wn2) {
    int i = blockIdx.x * blockDim.x + threadIdx.x;
    if (i < 8192) {
        int ks = i >> 9, tg = (i >> 7) & 3, n = i & 127;
        int k0 = ks * 8 + tg;
        g_w1tp[i] = make_uint2(f2tf(We1[k0 * 128 + n]),         f2tf(We1[(k0 + 4) * 128 + n]));
        g_w1bp[i] = make_uint2(f2tf(We1[(128 + k0) * 128 + n]), f2tf(We1[(132 + k0) * 128 + n]));
        g_w2ep[i] = make_uint2(f2tf(We2[k0 * 128 + n]),         f2tf(We2[(k0 + 4) * 128 + n]));
    }
    if (i < 32768)      g_w1n[i]          = f2tf(Wn1[i]);
    else if (i < 49152) g_w2n[i - 32768]  = f2tf(Wn2[i - 32768]);
}

// ---------------- CSR build -------------------------------------------------
__global__ void zero_kernel(int nq) {
    int i = blockIdx.x * blockDim.x + threadIdx.x;
    if (i < nq) g_counts[i] = 0;
    if (i < nq * DF) g_agg[i] = 0.f;
}
__global__ void hist_kernel(const int* __restrict__ ei, int E) {
    int e = blockIdx.x * blockDim.x + threadIdx.x;
    if (e < E) atomicAdd(&g_counts[ei[e]], 1);
}
__global__ void scan_kernel(int nq) {
    const int CH = 20;
    __shared__ int wt[32];
    int tid = threadIdx.x, lane = tid & 31, w = tid >> 5;
    int loc[CH]; int base = tid * CH; int s = 0;
#pragma unroll
    for (int i = 0; i < CH; i++) {
        loc[i] = (base + i < nq) ? g_counts[base + i] : 0; s += loc[i];
    }
    int v = s;
#pragma unroll
    for (int o = 1; o < 32; o <<= 1) { int t = __shfl_up_sync(~0u, v, o); if (lane >= o) v += t; }
    if (lane == 31) wt[w] = v;
    __syncthreads();
    if (w == 0) {
        int x = wt[lane];
#pragma unroll
        for (int o = 1; o < 32; o <<= 1) { int t = __shfl_up_sync(~0u, x, o); if (lane >= o) x += t; }
        wt[lane] = x;
    }
    __syncthreads();
    int ex = v + (w ? wt[w - 1] : 0) - s;
#pragma unroll
    for (int i = 0; i < CH; i++) {
        if (base + i < nq) { g_offsets[base + i] = ex; g_cursor[base + i] = ex; }
        ex += loc[i];
    }
    if (tid == 1023) g_offsets[nq] = ex;
}
__global__ void scatter_kernel(const int* __restrict__ ei, int E) {
    int e = blockIdx.x * blockDim.x + threadIdx.x;
    if (e < E) {
        int r = ei[e];
        int pos = atomicAdd(&g_cursor[r], 1);
        g_eids[pos] = e; g_erow[pos] = r;
    }
}

// ---------------- single-layer GEMM: P/Q precompute -------------------------
// SEL=0: g_P = src @ g_w1tp (+bias);  SEL=1: g_Q = src @ g_w1bp.
// Device symbols selected INSIDE device code (host-passed __device__ pointers are UB).
template <int SEL>
__global__ void __launch_bounds__(256, 2)
pq_kernel(const float* __restrict__ src, const float* __restrict__ bias, int nrows) {
    const uint2* __restrict__ Wp = (SEL == 0) ? g_w1tp : g_w1bp;
    float* __restrict__ dst      = (SEL == 0) ? g_P    : g_Q;
    extern __shared__ uint32_t As[];          // [128][LDA2]
    int tid = threadIdx.x;
    {
        int r = tid >> 1, half = tid & 1;
        int rowg = blockIdx.x * 128 + r;
        bool ok = rowg < nrows;
        const float4* s4 = (const float4*)(src + (size_t)(ok ? rowg : 0) * DF + half * 64);
#pragma unroll
        for (int j = 0; j < 16; j++) {
            float4 v = ok ? s4[j] : make_float4(0.f, 0.f, 0.f, 0.f);
            uint4 u; u.x = f2tf(v.x); u.y = f2tf(v.y); u.z = f2tf(v.z); u.w = f2tf(v.w);
            *(uint4*)&As[r * LDA2 + half * 64 + j * 4] = u;
        }
    }
    __syncthreads();

    int lane = tid & 31, wid = tid >> 5, gid = lane >> 2, tg = lane & 3;
    float acc[8][2][4];
    float bv[2][2];
#pragma unroll
    for (int nt = 0; nt < 2; nt++) {
        int col = wid * 16 + nt * 8 + tg * 2;
        bv[nt][0] = (SEL == 0) ? bias[col] : 0.f;
        bv[nt][1] = (SEL == 0) ? bias[col + 1] : 0.f;
    }
#pragma unroll
    for (int mt = 0; mt < 8; mt++)
#pragma unroll
        for (int nt = 0; nt < 2; nt++) {
            acc[mt][nt][0] = bv[nt][0]; acc[mt][nt][1] = bv[nt][1];
            acc[mt][nt][2] = bv[nt][0]; acc[mt][nt][3] = bv[nt][1];
        }
#pragma unroll
    for (int ks = 0; ks < 16; ks++) {
        uint2 b0 = Wp[(ks * 4 + tg) * 128 + wid * 16 + gid];
        uint2 b1 = Wp[(ks * 4 + tg) * 128 + wid * 16 + 8 + gid];
#pragma unroll
        for (int mt = 0; mt < 8; mt++) {
            uint32_t a[4];
            const uint32_t* ap = As + (mt * 16 + gid) * LDA2 + ks * 8 + tg;
            a[0] = ap[0]; a[1] = ap[8 * LDA2]; a[2] = ap[4]; a[3] = ap[8 * LDA2 + 4];
            mma8(acc[mt][0], a, b0.x, b0.y);
            mma8(acc[mt][1], a, b1.x, b1.y);
        }
    }
#pragma unroll
    for (int mt = 0; mt < 8; mt++) {
        int r0 = blockIdx.x * 128 + mt * 16 + gid, r1 = r0 + 8;
#pragma unroll
        for (int nt = 0; nt < 2; nt++) {
            int col = wid * 16 + nt * 8 + tg * 2;
            if (r0 < nrows) {
                dst[(size_t)r0 * DF + col] = acc[mt][nt][0];
                dst[(size_t)r0 * DF + col + 1] = acc[mt][nt][1];
            }
            if (r1 < nrows) {
                dst[(size_t)r1 * DF + col] = acc[mt][nt][2];
                dst[(size_t)r1 * DF + col + 1] = acc[mt][nt][3];
            }
        }
    }
}

// ---------------- edge layer-2: gather P+Q, silu, GEMM W2, store + agg ------
#define SMEM_E ((128 * LDA2 + 256) * 4)

__global__ void __launch_bounds__(256, 2)
edge_l2_kernel(const int* __restrict__ ei, int E,
               const float* __restrict__ b2, float* __restrict__ out_m) {
    extern __shared__ uint32_t S[];
    uint32_t* As = S;                         // [128][LDA2] tf32 H tile
    float*    Rb = (float*)S;                 // reused fp32 out staging
    int* s_eid = (int*)(S + 128 * LDA2);
    int* s_row = (int*)(S + 128 * LDA2 + 128);
    int tid = threadIdx.x;

    // ---- gather & build H = silu(P[row] + Q[col]) as tf32 ----
    {
        int r = tid >> 1, half = tid & 1;
        int ci = blockIdx.x * 128 + r;
        int eid = -1, row = 0, col = 0;
        if (ci < E) { eid = g_eids[ci]; row = g_erow[ci]; col = ei[E + eid]; }
        if (half == 0) { s_eid[r] = eid; s_row[r] = (eid >= 0) ? row : -1; }
        const float4* p4 = (const float4*)(g_P + (size_t)row * DF + half * 64);
        const float4* q4 = (const float4*)(g_Q + (size_t)col * DF + half * 64);
#pragma unroll
        for (int j = 0; j < 16; j++) {
            float4 p = (eid >= 0) ? p4[j] : make_float4(0.f, 0.f, 0.f, 0.f);
            float4 q = (eid >= 0) ? q4[j] : make_float4(0.f, 0.f, 0.f, 0.f);
            uint4 u;
            u.x = f2tf(silu(p.x + q.x)); u.y = f2tf(silu(p.y + q.y));
            u.z = f2tf(silu(p.z + q.z)); u.w = f2tf(silu(p.w + q.w));
            *(uint4*)&As[r * LDA2 + half * 64 + j * 4] = u;
        }
    }
    __syncthreads();

    int lane = tid & 31, wid = tid >> 5, gid = lane >> 2, tg = lane & 3;
    float acc[8][2][4];
    float bv[2][2];
#pragma unroll
    for (int nt = 0; nt < 2; nt++) {
        int col = wid * 16 + nt * 8 + tg * 2;
        bv[nt][0] = b2[col]; bv[nt][1] = b2[col + 1];
    }
#pragma unroll
    for (int mt = 0; mt < 8; mt++)
#pragma unroll
        for (int nt = 0; nt < 2; nt++) {
            acc[mt][nt][0] = bv[nt][0]; acc[mt][nt][1] = bv[nt][1];
            acc[mt][nt][2] = bv[nt][0]; acc[mt][nt][3] = bv[nt][1];
        }
#pragma unroll
    for (int ks = 0; ks < 16; ks++) {
        uint2 b0 = g_w2ep[(ks * 4 + tg) * 128 + wid * 16 + gid];
        uint2 b1 = g_w2ep[(ks * 4 + tg) * 128 + wid * 16 + 8 + gid];
#pragma unroll
        for (int mt = 0; mt < 8; mt++) {
            uint32_t a[4];
            const uint32_t* ap = As + (mt * 16 + gid) * LDA2 + ks * 8 + tg;
            a[0] = ap[0]; a[1] = ap[8 * LDA2]; a[2] = ap[4]; a[3] = ap[8 * LDA2 + 4];
            mma8(acc[mt][0], a, b0.x, b0.y);
            mma8(acc[mt][1], a, b1.x, b1.y);
        }
    }
    __syncthreads();   // all warps done reading As -> safe to overwrite with Rb

    // ---- silu -> Rb (fp32) ----
#pragma unroll
    for (int mt = 0; mt < 8; mt++) {
        int r0 = mt * 16 + gid, r1 = r0 + 8;
#pragma unroll
        for (int nt = 0; nt < 2; nt++) {
            int col = wid * 16 + nt * 8 + tg * 2;
            Rb[r0 * LDA2 + col]     = silu(acc[mt][nt][0]);
            Rb[r0 * LDA2 + col + 1] = silu(acc[mt][nt][1]);
            Rb[r1 * LDA2 + col]     = silu(acc[mt][nt][2]);
            Rb[r1 * LDA2 + col + 1] = silu(acc[mt][nt][3]);
        }
    }
    __syncthreads();

    // ---- coalesced mij store ----
#pragma unroll
    for (int rep = 0; rep < 16; rep++) {
        int i = tid + rep * 256;               // 4096 float4 = 128 rows x 32
        int row = i >> 5, c4 = i & 31;
        int eid = s_eid[row];
        if (eid >= 0)
            *(float4*)(out_m + (size_t)eid * DF + c4 * 4) = *(float4*)&Rb[row * LDA2 + c4 * 4];
    }

    // ---- fused segmented aggregation (CSR-sorted rows) ----
    {
        int col = tid & 127, half = tid >> 7;
        int cur = -1; float racc = 0.f;
#pragma unroll 4
        for (int r0 = 0; r0 < 64; r0++) {
            int r = half * 64 + r0;
            int rw = s_row[r];
            if (rw != cur) {
                if (cur >= 0) atomicAdd(&g_agg[(size_t)cur * DF + col], racc);
                cur = rw; racc = 0.f;
            }
            if (rw >= 0) racc += Rb[r * LDA2 + col];
        }
        if (cur >= 0) atomicAdd(&g_agg[(size_t)cur * DF + col], racc);
    }
}

// ---------------- node MLP (proven R3 path) ---------------------------------
#define LDA 260
#define SMEM_N (128 * LDA * 4)

__device__ __forceinline__ void mma_tiles(const uint32_t* __restrict__ As,
                                          const uint32_t* __restrict__ Bw,
                                          int ksteps, float acc[2][8][4],
                                          int warp_m, int warp_n, int gid, int tg) {
    for (int ks = 0; ks < ksteps; ks++) {
        int k0 = ks * 8;
        uint32_t a[2][4];
#pragma unroll
        for (int mt = 0; mt < 2; mt++) {
            const uint32_t* ap = As + (warp_m * 32 + mt * 16 + gid) * LDA + k0 + tg;
            a[mt][0] = ap[0]; a[mt][1] = ap[8 * LDA];
            a[mt][2] = ap[4]; a[mt][3] = ap[8 * LDA + 4];
        }
#pragma unroll
        for (int nt = 0; nt < 8; nt++) {
            int n = warp_n * 64 + nt * 8 + gid;
            uint32_t b0 = Bw[(k0 + tg) * 128 + n];
            uint32_t b1 = Bw[(k0 + tg + 4) * 128 + n];
#pragma unroll
            for (int mt = 0; mt < 2; mt++) mma8(acc[mt][nt], a[mt], b0, b1);
        }
    }
}
__global__ void __launch_bounds__(256, 1)
node_kernel(const float* __restrict__ Aq,
            const float* __restrict__ bias1, const float* __restrict__ bias2,
            float* __restrict__ outp, int nrows) {
    extern __shared__ uint32_t As[];
    int tid = threadIdx.x;
    {
        int r = tid >> 1, half = tid & 1;
        int rowg = blockIdx.x * 128 + r;
        bool ok = rowg < nrows;
        int n = ok ? rowg : 0;
        const float4* src = half ? (const float4*)(g_agg + (size_t)n * DF)
                                 : (const float4*)(Aq + (size_t)n * DF);
#pragma unroll
        for (int j = 0; j < 32; j++) {
            float4 v = ok ? src[j] : make_float4(0.f, 0.f, 0.f, 0.f);
            uint4 u; u.x = f2tf(v.x); u.y = f2tf(v.y); u.z = f2tf(v.z); u.w = f2tf(v.w);
            *(uint4*)&As[r * LDA + (half * 32 + j) * 4] = u;
        }
    }
    __syncthreads();
    int lane = tid & 31, wid = tid >> 5;
    int warp_m = wid >> 1, warp_n = wid & 1;
    int gid = lane >> 2, tg = lane & 3;

    float acc[2][8][4];
#pragma unroll
    for (int nt = 0; nt < 8; nt++) {
        int col = warp_n * 64 + nt * 8 + tg * 2;
        float b0 = bias1[col], b1 = bias1[col + 1];
#pragma unroll
        for (int mt = 0; mt < 2; mt++) {
            acc[mt][nt][0] = b0; acc[mt][nt][1] = b1;
            acc[mt][nt][2] = b0; acc[mt][nt][3] = b1;
        }
    }
    mma_tiles(As, g_w1n, 32, acc, warp_m, warp_n, gid, tg);
    __syncthreads();
#pragma unroll
    for (int mt = 0; mt < 2; mt++) {
        int row = warp_m * 32 + mt * 16 + gid;
#pragma unroll
        for (int nt = 0; nt < 8; nt++) {
            int col = warp_n * 64 + nt * 8 + tg * 2;
            As[row * LDA + col]           = f2tf(silu(acc[mt][nt][0]));
            As[row * LDA + col + 1]       = f2tf(silu(acc[mt][nt][1]));
            As[(row + 8) * LDA + col]     = f2tf(silu(acc[mt][nt][2]));
            As[(row + 8) * LDA + col + 1] = f2tf(silu(acc[mt][nt][3]));
        }
    }
    __syncthreads();
#pragma unroll
    for (int nt = 0; nt < 8; nt++) {
        int col = warp_n * 64 + nt * 8 + tg * 2;
        float b0 = bias2[col], b1 = bias2[col + 1];
#pragma unroll
        for (int mt = 0; mt < 2; mt++) {
            acc[mt][nt][0] = b0; acc[mt][nt][1] = b1;
            acc[mt][nt][2] = b0; acc[mt][nt][3] = b1;
        }
    }
    mma_tiles(As, g_w2n, 16, acc, warp_m, warp_n, gid, tg);
#pragma unroll
    for (int mt = 0; mt < 2; mt++) {
        int row = warp_m * 32 + mt * 16 + gid;
        int rg0 = blockIdx.x * 128 + row, rg1 = rg0 + 8;
#pragma unroll
        for (int nt = 0; nt < 8; nt++) {
            int col = warp_n * 64 + nt * 8 + tg * 2;
            if (rg0 < nrows) {
                const float* h = Aq + (size_t)rg0 * DF + col;
                float* o = outp + (size_t)rg0 * DF + col;
                o[0] = acc[mt][nt][0] + h[0]; o[1] = acc[mt][nt][1] + h[1];
            }
            if (rg1 < nrows) {
                const float* h = Aq + (size_t)rg1 * DF + col;
                float* o = outp + (size_t)rg1 * DF + col;
                o[0] = acc[mt][nt][2] + h[0]; o[1] = acc[mt][nt][3] + h[1];
            }
        }
    }
}

// ---------------- launch ----------------------------------------------------
extern "C" void kernel_launch(void* const* d_in, const int* in_sizes, int n_in,
                              void* d_out, int out_size) {
    const float* h_q  = (const float*)d_in[0];
    const float* h_kv = (const float*)d_in[1];
    const int*   ei   = (const int*)d_in[2];
    const float* We1  = (const float*)d_in[3];
    const float* be1  = (const float*)d_in[4];
    const float* We2  = (const float*)d_in[5];
    const float* be2  = (const float*)d_in[6];
    const float* Wn1  = (const float*)d_in[7];
    const float* bn1  = (const float*)d_in[8];
    const float* Wn2  = (const float*)d_in[9];
    const float* bn2  = (const float*)d_in[10];

    int nq  = in_sizes[0] / DF;
    int nkv = in_sizes[1] / DF;
    int E   = in_sizes[2] / 2;

    float* out_h = (float*)d_out;
    float* out_m = (float*)d_out + (size_t)nq * DF;

    const int PQ_SMEM = 128 * LDA2 * 4;
    cudaFuncSetAttribute(pq_kernel<0>,   cudaFuncAttributeMaxDynamicSharedMemorySize, PQ_SMEM);
    cudaFuncSetAttribute(pq_kernel<1>,   cudaFuncAttributeMaxDynamicSharedMemorySize, PQ_SMEM);
    cudaFuncSetAttribute(edge_l2_kernel, cudaFuncAttributeMaxDynamicSharedMemorySize, SMEM_E);
    cudaFuncSetAttribute(node_kernel,    cudaFuncAttributeMaxDynamicSharedMemorySize, SMEM_N);

    prep_weights<<<(49152 + 255) / 256, 256>>>(We1, We2, Wn1, Wn2);
    zero_kernel<<<(nq * DF + 255) / 256, 256>>>(nq);
    hist_kernel<<<(E + 255) / 256, 256>>>(ei, E);
    scan_kernel<<<1, 1024>>>(nq);
    scatter_kernel<<<(E + 255) / 256, 256>>>(ei, E);

    pq_kernel<0><<<(nq + 127) / 128, 256, PQ_SMEM>>>(h_q, be1, nq);
    pq_kernel<1><<<(nkv + 127) / 128, 256, PQ_SMEM>>>(h_kv, be1, nkv);

    edge_l2_kernel<<<(E + 127) / 128, 256, SMEM_E>>>(ei, E, be2, out_m);

    node_kernel<<<(nq + 127) / 128, 256, SMEM_N>>>(h_q, bn1, bn2, out_h, nq);
}

// round 9
// speedup vs baseline: 2.4417x; 1.0241x over previous
#include <cuda_runtime.h>
#include <cstdint>

#define NQ_CAP 20480          // padded to 1024*20 for the int4 scan
#define E_CAP  640000
#define DF     128
#define LDA2   132            // padded row stride (words) -> conflict-free frags

// ---------------- static device scratch -------------------------------------
__device__ int      g_counts [NQ_CAP];
__device__ int      g_cursor [NQ_CAP];
__device__ int      g_eids   [E_CAP];
__device__ int      g_erow   [E_CAP];
__device__ float    g_agg    [(size_t)NQ_CAP * DF];
__device__ float    g_P      [(size_t)NQ_CAP * DF];   // h_q @ We1_top + b1
__device__ float    g_Q      [(size_t)NQ_CAP * DF];   // h_kv @ We1_bot
__device__ uint2    g_w1tp[8192];   // packed tf32 frag pairs: [ks][tg][n]
__device__ uint2    g_w1bp[8192];
__device__ uint2    g_w2ep[8192];
__device__ uint32_t g_w1n[256 * 128];
__device__ uint32_t g_w2n[128 * 128];

// ---------------- helpers ---------------------------------------------------
__device__ __forceinline__ uint32_t f2tf(float x) {
    uint32_t u; asm("cvt.rna.tf32.f32 %0, %1;" : "=r"(u) : "f"(x)); return u;
}
__device__ __forceinline__ float silu(float x) { return x / (1.0f + __expf(-x)); }
__device__ __forceinline__ void mma8(float c[4], const uint32_t a[4],
                                     uint32_t b0, uint32_t b1) {
    asm("mma.sync.aligned.m16n8k8.row.col.f32.tf32.tf32.f32 "
        "{%0,%1,%2,%3}, {%4,%5,%6,%7}, {%8,%9}, {%0,%1,%2,%3};"
        : "+f"(c[0]), "+f"(c[1]), "+f"(c[2]), "+f"(c[3])
        : "r"(a[0]), "r"(a[1]), "r"(a[2]), "r"(a[3]), "r"(b0), "r"(b1));
}

// ---------------- prep: pack weights + zero counts/agg (merged) -------------
__global__ void prep_zero_kernel(const float* __restrict__ We1,
                                 const float* __restrict__ We2,
                                 const float* __restrict__ Wn1,
                                 const float* __restrict__ Wn2, int nq) {
    int i = blockIdx.x * blockDim.x + threadIdx.x;
    if (i < 8192) {
        int ks = i >> 9, tg = (i >> 7) & 3, n = i & 127;
        int k0 = ks * 8 + tg;
        g_w1tp[i] = make_uint2(f2tf(We1[k0 * 128 + n]),         f2tf(We1[(k0 + 4) * 128 + n]));
        g_w1bp[i] = make_uint2(f2tf(We1[(128 + k0) * 128 + n]), f2tf(We1[(132 + k0) * 128 + n]));
        g_w2ep[i] = make_uint2(f2tf(We2[k0 * 128 + n]),         f2tf(We2[(k0 + 4) * 128 + n]));
    }
    if (i < 32768)      g_w1n[i]          = f2tf(Wn1[i]);
    else if (i < 49152) g_w2n[i - 32768]  = f2tf(Wn2[i - 32768]);
    if (i < NQ_CAP) g_counts[i] = 0;
    if (i < nq * DF) g_agg[i] = 0.f;
}

// ---------------- CSR build -------------------------------------------------
__global__ void hist_kernel(const int* __restrict__ ei, int E) {
    int e = blockIdx.x * blockDim.x + threadIdx.x;
    if (e < E) atomicAdd(&g_counts[ei[e]], 1);
}
// int4 scan: 1024 threads x 20 counts -> exclusive prefix into g_cursor only.
__global__ void scan_kernel() {
    __shared__ int wt[32];
    int tid = threadIdx.x, lane = tid & 31, w = tid >> 5;
    int base = tid * 20;
    int4 c[5];
#pragma unroll
    for (int i = 0; i < 5; i++) c[i] = *(const int4*)&g_counts[base + i * 4];
    int s = 0;
#pragma unroll
    for (int i = 0; i < 5; i++) s += c[i].x + c[i].y + c[i].z + c[i].w;
    int v = s;
#pragma unroll
    for (int o = 1; o < 32; o <<= 1) { int t = __shfl_up_sync(~0u, v, o); if (lane >= o) v += t; }
    if (lane == 31) wt[w] = v;
    __syncthreads();
    if (w == 0) {
        int x = wt[lane];
#pragma unroll
        for (int o = 1; o < 32; o <<= 1) { int t = __shfl_up_sync(~0u, x, o); if (lane >= o) x += t; }
        wt[lane] = x;
    }
    __syncthreads();
    int ex = v + (w ? wt[w - 1] : 0) - s;
#pragma unroll
    for (int i = 0; i < 5; i++) {
        int4 o;
        o.x = ex; o.y = ex + c[i].x; o.z = o.y + c[i].y; o.w = o.z + c[i].z;
        *(int4*)&g_cursor[base + i * 4] = o;
        ex = o.w + c[i].w;
    }
}
__global__ void scatter_kernel(const int* __restrict__ ei, int E) {
    int e = blockIdx.x * blockDim.x + threadIdx.x;
    if (e < E) {
        int r = ei[e];
        int pos = atomicAdd(&g_cursor[r], 1);
        g_eids[pos] = e; g_erow[pos] = r;
    }
}

// ---------------- single-layer GEMM: P/Q precompute -------------------------
template <int SEL>
__global__ void __launch_bounds__(256, 2)
pq_kernel(const float* __restrict__ src, const float* __restrict__ bias, int nrows) {
    const uint2* __restrict__ Wp = (SEL == 0) ? g_w1tp : g_w1bp;
    float* __restrict__ dst      = (SEL == 0) ? g_P    : g_Q;
    extern __shared__ uint32_t As[];          // [128][LDA2]
    int tid = threadIdx.x;
    {
        int r = tid >> 1, half = tid & 1;
        int rowg = blockIdx.x * 128 + r;
        bool ok = rowg < nrows;
        const float4* s4 = (const float4*)(src + (size_t)(ok ? rowg : 0) * DF + half * 64);
#pragma unroll
        for (int j = 0; j < 16; j++) {
            float4 v = ok ? s4[j] : make_float4(0.f, 0.f, 0.f, 0.f);
            uint4 u; u.x = f2tf(v.x); u.y = f2tf(v.y); u.z = f2tf(v.z); u.w = f2tf(v.w);
            *(uint4*)&As[r * LDA2 + half * 64 + j * 4] = u;
        }
    }
    __syncthreads();

    int lane = tid & 31, wid = tid >> 5, gid = lane >> 2, tg = lane & 3;
    float acc[8][2][4];
    float bv[2][2];
#pragma unroll
    for (int nt = 0; nt < 2; nt++) {
        int col = wid * 16 + nt * 8 + tg * 2;
        bv[nt][0] = (SEL == 0) ? bias[col] : 0.f;
        bv[nt][1] = (SEL == 0) ? bias[col + 1] : 0.f;
    }
#pragma unroll
    for (int mt = 0; mt < 8; mt++)
#pragma unroll
        for (int nt = 0; nt < 2; nt++) {
            acc[mt][nt][0] = bv[nt][0]; acc[mt][nt][1] = bv[nt][1];
            acc[mt][nt][2] = bv[nt][0]; acc[mt][nt][3] = bv[nt][1];
        }
#pragma unroll
    for (int ks = 0; ks < 16; ks++) {
        uint2 b0 = Wp[(ks * 4 + tg) * 128 + wid * 16 + gid];
        uint2 b1 = Wp[(ks * 4 + tg) * 128 + wid * 16 + 8 + gid];
#pragma unroll
        for (int mt = 0; mt < 8; mt++) {
            uint32_t a[4];
            const uint32_t* ap = As + (mt * 16 + gid) * LDA2 + ks * 8 + tg;
            a[0] = ap[0]; a[1] = ap[8 * LDA2]; a[2] = ap[4]; a[3] = ap[8 * LDA2 + 4];
            mma8(acc[mt][0], a, b0.x, b0.y);
            mma8(acc[mt][1], a, b1.x, b1.y);
        }
    }
#pragma unroll
    for (int mt = 0; mt < 8; mt++) {
        int r0 = blockIdx.x * 128 + mt * 16 + gid, r1 = r0 + 8;
#pragma unroll
        for (int nt = 0; nt < 2; nt++) {
            int col = wid * 16 + nt * 8 + tg * 2;
            if (r0 < nrows) {
                dst[(size_t)r0 * DF + col] = acc[mt][nt][0];
                dst[(size_t)r0 * DF + col + 1] = acc[mt][nt][1];
            }
            if (r1 < nrows) {
                dst[(size_t)r1 * DF + col] = acc[mt][nt][2];
                dst[(size_t)r1 * DF + col + 1] = acc[mt][nt][3];
            }
        }
    }
}

// ---------------- edge layer-2: 64-edge tiles, occupancy 3 ------------------
// SMEM: As/Rb [64][LDA2] + s_eid[64] + s_row[64]
#define SMEM_E ((64 * LDA2 + 128) * 4)

__global__ void __launch_bounds__(256, 3)
edge_l2_kernel(const int* __restrict__ ei, int E,
               const float* __restrict__ b2, float* __restrict__ out_m) {
    extern __shared__ uint32_t S[];
    uint32_t* As = S;                         // [64][LDA2] tf32 H tile
    float*    Rb = (float*)S;                 // reused fp32 out staging
    int* s_eid = (int*)(S + 64 * LDA2);
    int* s_row = (int*)(S + 64 * LDA2 + 64);
    int tid = threadIdx.x;

    // ---- gather & build H = silu(P[row] + Q[col]) as tf32 ----
    {
        int r = tid >> 2, q = tid & 3;        // 64 rows x 4 threads/row
        int ci = blockIdx.x * 64 + r;
        int eid = -1, row = 0, col = 0;
        if (ci < E) { eid = g_eids[ci]; row = g_erow[ci]; col = ei[E + eid]; }
        if (q == 0) { s_eid[r] = eid; s_row[r] = (eid >= 0) ? row : -1; }
        const float4* p4 = (const float4*)(g_P + (size_t)row * DF + q * 32);
        const float4* q4 = (const float4*)(g_Q + (size_t)col * DF + q * 32);
#pragma unroll
        for (int j = 0; j < 8; j++) {
            float4 p = (eid >= 0) ? p4[j] : make_float4(0.f, 0.f, 0.f, 0.f);
            float4 qq = (eid >= 0) ? q4[j] : make_float4(0.f, 0.f, 0.f, 0.f);
            uint4 u;
            u.x = f2tf(silu(p.x + qq.x)); u.y = f2tf(silu(p.y + qq.y));
            u.z = f2tf(silu(p.z + qq.z)); u.w = f2tf(silu(p.w + qq.w));
            *(uint4*)&As[r * LDA2 + q * 32 + j * 4] = u;
        }
    }
    __syncthreads();

    int lane = tid & 31, wid = tid >> 5, gid = lane >> 2, tg = lane & 3;
    float acc[4][2][4];
#pragma unroll
    for (int nt = 0; nt < 2; nt++) {
        int col = wid * 16 + nt * 8 + tg * 2;
        float b0 = b2[col], b1 = b2[col + 1];
#pragma unroll
        for (int mt = 0; mt < 4; mt++) {
            acc[mt][nt][0] = b0; acc[mt][nt][1] = b1;
            acc[mt][nt][2] = b0; acc[mt][nt][3] = b1;
        }
    }
#pragma unroll
    for (int ks = 0; ks < 16; ks++) {
        uint2 b0 = g_w2ep[(ks * 4 + tg) * 128 + wid * 16 + gid];
        uint2 b1 = g_w2ep[(ks * 4 + tg) * 128 + wid * 16 + 8 + gid];
#pragma unroll
        for (int mt = 0; mt < 4; mt++) {
            uint32_t a[4];
            const uint32_t* ap = As + (mt * 16 + gid) * LDA2 + ks * 8 + tg;
            a[0] = ap[0]; a[1] = ap[8 * LDA2]; a[2] = ap[4]; a[3] = ap[8 * LDA2 + 4];
            mma8(acc[mt][0], a, b0.x, b0.y);
            mma8(acc[mt][1], a, b1.x, b1.y);
        }
    }
    __syncthreads();   // all warps done reading As -> safe to overwrite with Rb

    // ---- silu -> Rb (fp32) ----
#pragma unroll
    for (int mt = 0; mt < 4; mt++) {
        int r0 = mt * 16 + gid, r1 = r0 + 8;
#pragma unroll
        for (int nt = 0; nt < 2; nt++) {
            int col = wid * 16 + nt * 8 + tg * 2;
            Rb[r0 * LDA2 + col]     = silu(acc[mt][nt][0]);
            Rb[r0 * LDA2 + col + 1] = silu(acc[mt][nt][1]);
            Rb[r1 * LDA2 + col]     = silu(acc[mt][nt][2]);
            Rb[r1 * LDA2 + col + 1] = silu(acc[mt][nt][3]);
        }
    }
    __syncthreads();

    // ---- coalesced mij store ----
#pragma unroll
    for (int rep = 0; rep < 8; rep++) {
        int i = tid + rep * 256;               // 2048 float4 = 64 rows x 32
        int row = i >> 5, c4 = i & 31;
        int eid = s_eid[row];
        if (eid >= 0)
            *(float4*)(out_m + (size_t)eid * DF + c4 * 4) = *(float4*)&Rb[row * LDA2 + c4 * 4];
    }

    // ---- fused segmented aggregation (CSR-sorted rows) ----
    {
        int col = tid & 127, half = tid >> 7;
        int cur = -1; float racc = 0.f;
#pragma unroll 4
        for (int r0 = 0; r0 < 32; r0++) {
            int r = half * 32 + r0;
            int rw = s_row[r];
            if (rw != cur) {
                if (cur >= 0) atomicAdd(&g_agg[(size_t)cur * DF + col], racc);
                cur = rw; racc = 0.f;
            }
            if (rw >= 0) racc += Rb[r * LDA2 + col];
        }
        if (cur >= 0) atomicAdd(&g_agg[(size_t)cur * DF + col], racc);
    }
}

// ---------------- node MLP (proven R3 path, unchanged) ----------------------
#define LDA 260
#define SMEM_N (128 * LDA * 4)

__device__ __forceinline__ void mma_tiles(const uint32_t* __restrict__ As,
                                          const uint32_t* __restrict__ Bw,
                                          int ksteps, float acc[2][8][4],
                                          int warp_m, int warp_n, int gid, int tg) {
    for (int ks = 0; ks < ksteps; ks++) {
        int k0 = ks * 8;
        uint32_t a[2][4];
#pragma unroll
        for (int mt = 0; mt < 2; mt++) {
            const uint32_t* ap = As + (warp_m * 32 + mt * 16 + gid) * LDA + k0 + tg;
            a[mt][0] = ap[0]; a[mt][1] = ap[8 * LDA];
            a[mt][2] = ap[4]; a[mt][3] = ap[8 * LDA + 4];
        }
#pragma unroll
        for (int nt = 0; nt < 8; nt++) {
            int n = warp_n * 64 + nt * 8 + gid;
            uint32_t b0 = Bw[(k0 + tg) * 128 + n];
            uint32_t b1 = Bw[(k0 + tg + 4) * 128 + n];
#pragma unroll
            for (int mt = 0; mt < 2; mt++) mma8(acc[mt][nt], a[mt], b0, b1);
        }
    }
}
__global__ void __launch_bounds__(256, 1)
node_kernel(const float* __restrict__ Aq,
            const float* __restrict__ bias1, const float* __restrict__ bias2,
            float* __restrict__ outp, int nrows) {
    extern __shared__ uint32_t As[];
    int tid = threadIdx.x;
    {
        int r = tid >> 1, half = tid & 1;
        int rowg = blockIdx.x * 128 + r;
        bool ok = rowg < nrows;
        int n = ok ? rowg : 0;
        const float4* src = half ? (const float4*)(g_agg + (size_t)n * DF)
                                 : (const float4*)(Aq + (size_t)n * DF);
#pragma unroll
        for (int j = 0; j < 32; j++) {
            float4 v = ok ? src[j] : make_float4(0.f, 0.f, 0.f, 0.f);
            uint4 u; u.x = f2tf(v.x); u.y = f2tf(v.y); u.z = f2tf(v.z); u.w = f2tf(v.w);
            *(uint4*)&As[r * LDA + (half * 32 + j) * 4] = u;
        }
    }
    __syncthreads();
    int lane = tid & 31, wid = tid >> 5;
    int warp_m = wid >> 1, warp_n = wid & 1;
    int gid = lane >> 2, tg = lane & 3;

    float acc[2][8][4];
#pragma unroll
    for (int nt = 0; nt < 8; nt++) {
        int col = warp_n * 64 + nt * 8 + tg * 2;
        float b0 = bias1[col], b1 = bias1[col + 1];
#pragma unroll
        for (int mt = 0; mt < 2; mt++) {
            acc[mt][nt][0] = b0; acc[mt][nt][1] = b1;
            acc[mt][nt][2] = b0; acc[mt][nt][3] = b1;
        }
    }
    mma_tiles(As, g_w1n, 32, acc, warp_m, warp_n, gid, tg);
    __syncthreads();
#pragma unroll
    for (int mt = 0; mt < 2; mt++) {
        int row = warp_m * 32 + mt * 16 + gid;
#pragma unroll
        for (int nt = 0; nt < 8; nt++) {
            int col = warp_n * 64 + nt * 8 + tg * 2;
            As[row * LDA + col]           = f2tf(silu(acc[mt][nt][0]));
            As[row * LDA + col + 1]       = f2tf(silu(acc[mt][nt][1]));
            As[(row + 8) * LDA + col]     = f2tf(silu(acc[mt][nt][2]));
            As[(row + 8) * LDA + col + 1] = f2tf(silu(acc[mt][nt][3]));
        }
    }
    __syncthreads();
#pragma unroll
    for (int nt = 0; nt < 8; nt++) {
        int col = warp_n * 64 + nt * 8 + tg * 2;
        float b0 = bias2[col], b1 = bias2[col + 1];
#pragma unroll
        for (int mt = 0; mt < 2; mt++) {
            acc[mt][nt][0] = b0; acc[mt][nt][1] = b1;
            acc[mt][nt][2] = b0; acc[mt][nt][3] = b1;
        }
    }
    mma_tiles(As, g_w2n, 16, acc, warp_m, warp_n, gid, tg);
#pragma unroll
    for (int mt = 0; mt < 2; mt++) {
        int row = warp_m * 32 + mt * 16 + gid;
        int rg0 = blockIdx.x * 128 + row, rg1 = rg0 + 8;
#pragma unroll
        for (int nt = 0; nt < 8; nt++) {
            int col = warp_n * 64 + nt * 8 + tg * 2;
            if (rg0 < nrows) {
                const float* h = Aq + (size_t)rg0 * DF + col;
                float* o = outp + (size_t)rg0 * DF + col;
                o[0] = acc[mt][nt][0] + h[0]; o[1] = acc[mt][nt][1] + h[1];
            }
            if (rg1 < nrows) {
                const float* h = Aq + (size_t)rg1 * DF + col;
                float* o = outp + (size_t)rg1 * DF + col;
                o[0] = acc[mt][nt][2] + h[0]; o[1] = acc[mt][nt][3] + h[1];
            }
        }
    }
}

// ---------------- launch ----------------------------------------------------
extern "C" void kernel_launch(void* const* d_in, const int* in_sizes, int n_in,
                              void* d_out, int out_size) {
    const float* h_q  = (const float*)d_in[0];
    const float* h_kv = (const float*)d_in[1];
    const int*   ei   = (const int*)d_in[2];
    const float* We1  = (const float*)d_in[3];
    const float* be1  = (const float*)d_in[4];
    const float* We2  = (const float*)d_in[5];
    const float* be2  = (const float*)d_in[6];
    const float* Wn1  = (const float*)d_in[7];
    const float* bn1  = (const float*)d_in[8];
    const float* Wn2  = (const float*)d_in[9];
    const float* bn2  = (const float*)d_in[10];

    int nq  = in_sizes[0] / DF;
    int nkv = in_sizes[1] / DF;
    int E   = in_sizes[2] / 2;

    float* out_h = (float*)d_out;
    float* out_m = (float*)d_out + (size_t)nq * DF;

    const int PQ_SMEM = 128 * LDA2 * 4;
    cudaFuncSetAttribute(pq_kernel<0>,   cudaFuncAttributeMaxDynamicSharedMemorySize, PQ_SMEM);
    cudaFuncSetAttribute(pq_kernel<1>,   cudaFuncAttributeMaxDynamicSharedMemorySize, PQ_SMEM);
    cudaFuncSetAttribute(edge_l2_kernel, cudaFuncAttributeMaxDynamicSharedMemorySize, SMEM_E);
    cudaFuncSetAttribute(node_kernel,    cudaFuncAttributeMaxDynamicSharedMemorySize, SMEM_N);

    prep_zero_kernel<<<(nq * DF + 255) / 256, 256>>>(We1, We2, Wn1, Wn2, nq);
    hist_kernel<<<(E + 255) / 256, 256>>>(ei, E);
    scan_kernel<<<1, 1024>>>();
    scatter_kernel<<<(E + 255) / 256, 256>>>(ei, E);

    pq_kernel<0><<<(nq + 127) / 128, 256, PQ_SMEM>>>(h_q, be1, nq);
    pq_kernel<1><<<(nkv + 127) / 128, 256, PQ_SMEM>>>(h_kv, be1, nkv);

    edge_l2_kernel<<<(E + 63) / 64, 256, SMEM_E>>>(ei, E, be2, out_m);

    node_kernel<<<(nq + 127) / 128, 256, SMEM_N>>>(h_q, bn1, bn2, out_h, nq);
}